// round 5
// baseline (speedup 1.0000x reference)
#include <cuda_runtime.h>

#define KS 7
#define PAD 3
#define TILE_W 128
#define TILE_H 64
#define SW 136                     // staged row: gx in [bx-4, bx+132)
#define SH 70
#define ROW_CHUNKS 34              // 34 x 16B per row
#define TCHUNKS (SH * ROW_CHUNKS)  // 2380
#define NTILES 2048                // 8x * 16y * 16b
#define GRID_CTAS 304              // 2 per SM
#define BUF_FLOATS (SH * SW)       // 9520
#define SMEM_BYTES (2 * BUF_FLOATS * 4 + 49 * 8)

typedef unsigned long long u64;

__device__ __forceinline__ u64 pk2(float lo, float hi) {
    u64 r; asm("mov.b64 %0, {%1,%2};" : "=l"(r) : "f"(lo), "f"(hi)); return r;
}
__device__ __forceinline__ void fma2(u64& d, u64 a, u64 b) {
    asm("fma.rn.f32x2 %0, %1, %2, %0;" : "+l"(d) : "l"(a), "l"(b));
}
__device__ __forceinline__ void unpk2(u64 v, float& lo, float& hi) {
    asm("mov.b64 {%0,%1}, %2;" : "=f"(lo), "=f"(hi) : "l"(v));
}
__device__ __forceinline__ void cpa16(unsigned dst, const float* src, unsigned nbytes) {
    asm volatile("cp.async.ca.shared.global [%0], [%1], 16, %2;"
                 :: "r"(dst), "l"(src), "r"(nbytes) : "memory");
}

extern __shared__ float smem[];

__device__ __forceinline__ void stage_tile(const float* __restrict__ img, int t,
                                           unsigned sbuf, int tid) {
    int b   = t >> 7;
    int rem = t & 127;
    int by  = (rem >> 3) * TILE_H;
    int bx  = (rem & 7) * TILE_W;
    const float* src = img + ((size_t)b * 3 + 2) * (size_t)(1024 * 1024); // last channel

    #pragma unroll
    for (int k = 0; k < 5; k++) {
        int i = tid + k * 512;
        if (i < TCHUNKS) {
            int r  = i / ROW_CHUNKS;
            int c  = i - r * ROW_CHUNKS;
            int gy = by + r - PAD;
            int gx = bx - 4 + c * 4;
            unsigned ok = ((unsigned)gy < 1024u && (unsigned)gx < 1024u) ? 16u : 0u;
            const float* p = src + (size_t)(gy & 1023) * 1024 + (gx & 1023);
            cpa16(sbuf + (unsigned)(r * SW + c * 4) * 4u, p, ok);
        }
    }
    asm volatile("cp.async.commit_group;" ::: "memory");
}

__global__ __launch_bounds__(512, 2)
void Conv_8443905704574_kernel(const float* __restrict__ img,
                               const float* __restrict__ ker,
                               float* __restrict__ out) {
    const int tid = threadIdx.x;
    float* buf0 = smem;
    float* buf1 = smem + BUF_FLOATS;
    u64*   kw2  = (u64*)(smem + 2 * BUF_FLOATS);

    if (tid < 49) {
        float w = ker[tid];
        kw2[tid] = pk2(w, w);
    }

    unsigned sbase;
    asm("{ .reg .u64 t; cvta.to.shared.u64 t, %1; cvt.u32.u64 %0, t; }"
        : "=r"(sbase) : "l"(smem));
    const unsigned sb0 = sbase;
    const unsigned sb1 = sbase + BUF_FLOATS * 4;

    const int tx   = tid & 15;    // 16 threads x 8 px = 128 cols
    const int ty   = tid >> 4;    // 0..31
    const int row0 = ty * 2;      // 2 output rows per thread

    int t = blockIdx.x;
    if (t < NTILES) stage_tile(img, t, sb0, tid);
    int cur = 0;

    while (t < NTILES) {
        int nxt = t + GRID_CTAS;
        if (nxt < NTILES) {
            stage_tile(img, nxt, cur ? sb0 : sb1, tid);
            asm volatile("cp.async.wait_group 1;" ::: "memory");
        } else {
            asm volatile("cp.async.wait_group 0;" ::: "memory");
        }
        __syncthreads();

        const float* B = cur ? buf1 : buf0;

        // acc[o][p] = output pixels (2p, 2p+1) of output row (row0+o)
        u64 acc[2][4];
        #pragma unroll
        for (int o = 0; o < 2; o++)
            #pragma unroll
            for (int p = 0; p < 4; p++) acc[o][p] = 0ull;

        // Sliding 8-row window; each input row loaded once, feeds up to 2 output rows.
        #pragma unroll
        for (int r = 0; r < 8; r++) {
            const float* row = B + (row0 + r) * SW + tx * 8;
            float4 A0 = *(const float4*)(row);
            float4 A1 = *(const float4*)(row + 4);
            float4 A2 = *(const float4*)(row + 8);
            float4 A3 = *(const float4*)(row + 12);
            float v[16] = {A0.x, A0.y, A0.z, A0.w, A1.x, A1.y, A1.z, A1.w,
                           A2.x, A2.y, A2.z, A2.w, A3.x, A3.y, A3.z, A3.w};
            u64 P[14];
            #pragma unroll
            for (int i = 1; i <= 13; i++) P[i] = pk2(v[i], v[i + 1]);

            #pragma unroll
            for (int o = 0; o < 2; o++) {
                const int ky = r - o;
                if (ky >= 0 && ky < KS) {
                    #pragma unroll
                    for (int kx = 0; kx < KS; kx++) {
                        u64 ww = kw2[ky * 7 + kx];   // LDS.64 broadcast, feeds 4 fma2
                        fma2(acc[o][0], P[1 + kx], ww);
                        fma2(acc[o][1], P[3 + kx], ww);
                        fma2(acc[o][2], P[5 + kx], ww);
                        fma2(acc[o][3], P[7 + kx], ww);
                    }
                }
            }
        }

        // store: 8 px per row -> 2 STG.128 per row per channel, streaming hint
        int b   = t >> 7;
        int rem = t & 127;
        int by  = (rem >> 3) * TILE_H;
        int bx  = (rem & 7) * TILE_W;
        int ox  = bx + tx * 8;
        size_t obase = (size_t)b * 3 * 1024 * 1024;
        #pragma unroll
        for (int o = 0; o < 2; o++) {
            float4 lo4, hi4;
            unpk2(acc[o][0], lo4.x, lo4.y);
            unpk2(acc[o][1], lo4.z, lo4.w);
            unpk2(acc[o][2], hi4.x, hi4.y);
            unpk2(acc[o][3], hi4.z, hi4.w);
            size_t off = obase + (size_t)(by + row0 + o) * 1024 + ox;
            #pragma unroll
            for (int c = 0; c < 3; c++) {
                __stcs((float4*)(out + off + (size_t)c * 1024 * 1024),     lo4);
                __stcs((float4*)(out + off + (size_t)c * 1024 * 1024 + 4), hi4);
            }
        }

        __syncthreads();   // buffer reuse protection
        cur ^= 1;
        t = nxt;
    }
}

extern "C" void kernel_launch(void* const* d_in, const int* in_sizes, int n_in,
                              void* d_out, int out_size) {
    const float* img = (const float*)d_in[0];
    const float* ker = (const float*)d_in[1];
    float* out = (float*)d_out;

    cudaFuncSetAttribute(Conv_8443905704574_kernel,
                         cudaFuncAttributeMaxDynamicSharedMemorySize, SMEM_BYTES);
    Conv_8443905704574_kernel<<<GRID_CTAS, 512, SMEM_BYTES>>>(img, ker, out);
}

// round 7
// speedup vs baseline: 1.2248x; 1.2248x over previous
#include <cuda_runtime.h>

#define KS 7
#define PAD 3
#define TILE_W 128
#define TILE_H 128
#define SW 136                     // staged row: gx in [bx-4, bx+132)
#define SH 134                     // 128 + 6 halo rows
#define ROW_CHUNKS 34              // 34 x 16B per row
#define TCHUNKS (SH * ROW_CHUNKS)  // 4556
#define NTILES 1024                // 8x * 8y * 16b
#define GRID_CTAS 152              // 1 per SM
#define BUF_FLOATS (SH * SW)       // 18224
#define SMEM_BYTES (2 * BUF_FLOATS * 4 + 49 * 8)

typedef unsigned long long u64;

__device__ __forceinline__ u64 pk2(float lo, float hi) {
    u64 r; asm("mov.b64 %0, {%1,%2};" : "=l"(r) : "f"(lo), "f"(hi)); return r;
}
__device__ __forceinline__ void fma2(u64& d, u64 a, u64 b) {
    asm("fma.rn.f32x2 %0, %1, %2, %0;" : "+l"(d) : "l"(a), "l"(b));
}
__device__ __forceinline__ void unpk2(u64 v, float& lo, float& hi) {
    asm("mov.b64 {%0,%1}, %2;" : "=f"(lo), "=f"(hi) : "l"(v));
}
__device__ __forceinline__ void cpa16(unsigned dst, const float* src, unsigned nbytes) {
    asm volatile("cp.async.ca.shared.global [%0], [%1], 16, %2;"
                 :: "r"(dst), "l"(src), "r"(nbytes) : "memory");
}

extern __shared__ float smem[];

__device__ __forceinline__ void stage_tile(const float* __restrict__ img, int t,
                                           unsigned sbuf, int tid) {
    int b   = t >> 6;
    int rem = t & 63;
    int by  = (rem >> 3) * TILE_H;
    int bx  = (rem & 7) * TILE_W;
    const float* src = img + ((size_t)b * 3 + 2) * (size_t)(1024 * 1024); // last channel

    #pragma unroll
    for (int k = 0; k < 9; k++) {
        int i = tid + k * 512;
        if (i < TCHUNKS) {
            int r  = i / ROW_CHUNKS;
            int c  = i - r * ROW_CHUNKS;
            int gy = by + r - PAD;
            int gx = bx - 4 + c * 4;
            unsigned ok = ((unsigned)gy < 1024u && (unsigned)gx < 1024u) ? 16u : 0u;
            const float* p = src + (size_t)(gy & 1023) * 1024 + (gx & 1023);
            cpa16(sbuf + (unsigned)(r * SW + c * 4) * 4u, p, ok);
        }
    }
    asm volatile("cp.async.commit_group;" ::: "memory");
}

__global__ __launch_bounds__(512, 1)
void Conv_8443905704574_kernel(const float* __restrict__ img,
                               const float* __restrict__ ker,
                               float* __restrict__ out) {
    const int tid = threadIdx.x;
    float* buf0 = smem;
    float* buf1 = smem + BUF_FLOATS;
    u64*   kw2  = (u64*)(smem + 2 * BUF_FLOATS);

    if (tid < 49) {
        float w = ker[tid];
        kw2[tid] = pk2(w, w);
    }

    unsigned sbase;
    asm("{ .reg .u64 t; cvta.to.shared.u64 t, %1; cvt.u32.u64 %0, t; }"
        : "=r"(sbase) : "l"(smem));
    const unsigned sb0 = sbase;
    const unsigned sb1 = sbase + BUF_FLOATS * 4;

    const int tx   = tid & 31;    // 32 threads x 4 px = 128 cols (conflict-free 16B/lane)
    const int ty   = tid >> 5;    // 0..15
    const int row0 = ty * 4;      // group A rows: row0..row0+3; group B: +64

    int t = blockIdx.x;
    if (t < NTILES) stage_tile(img, t, sb0, tid);
    int cur = 0;

    while (t < NTILES) {
        int nxt = t + GRID_CTAS;
        if (nxt < NTILES) {
            stage_tile(img, nxt, cur ? sb0 : sb1, tid);
            asm volatile("cp.async.wait_group 1;" ::: "memory");
        } else {
            asm volatile("cp.async.wait_group 0;" ::: "memory");
        }
        __syncthreads();

        const float* B = cur ? buf1 : buf0;

        // acc[g][o][h]: group g, output row o, pixel-pair h (px01 / px23)
        u64 acc[2][4][2];
        #pragma unroll
        for (int g = 0; g < 2; g++)
            #pragma unroll
            for (int o = 0; o < 4; o++) { acc[g][o][0] = 0ull; acc[g][o][1] = 0ull; }

        // Sliding 10-row window over both y-groups simultaneously; each
        // weight broadcast feeds 4 fma2 (2 groups x 2 pixel-pairs).
        #pragma unroll
        for (int r = 0; r < 10; r++) {
            const float* rowA = B + (row0 + r) * SW + tx * 4;
            const float* rowB = rowA + 64 * SW;

            // need v[1..10] -> load 12 floats (3x float4); v[11] unused
            float4 a0 = *(const float4*)(rowA);
            float4 a1 = *(const float4*)(rowA + 4);
            float4 a2 = *(const float4*)(rowA + 8);
            float4 b0 = *(const float4*)(rowB);
            float4 b1 = *(const float4*)(rowB + 4);
            float4 b2 = *(const float4*)(rowB + 8);

            float va[12] = {a0.x, a0.y, a0.z, a0.w, a1.x, a1.y, a1.z, a1.w,
                            a2.x, a2.y, a2.z, a2.w};
            float vb[12] = {b0.x, b0.y, b0.z, b0.w, b1.x, b1.y, b1.z, b1.w,
                            b2.x, b2.y, b2.z, b2.w};

            u64 PA[9], PB[9];
            #pragma unroll
            for (int i = 0; i < 9; i++) {
                PA[i] = pk2(va[i + 1], va[i + 2]);
                PB[i] = pk2(vb[i + 1], vb[i + 2]);
            }

            #pragma unroll
            for (int o = 0; o < 4; o++) {
                const int ky = r - o;
                if (ky >= 0 && ky < KS) {
                    #pragma unroll
                    for (int kx = 0; kx < KS; kx++) {
                        u64 ww = kw2[ky * 7 + kx];   // LDS.64 broadcast -> 4 fma2
                        fma2(acc[0][o][0], PA[kx],     ww);
                        fma2(acc[0][o][1], PA[kx + 2], ww);
                        fma2(acc[1][o][0], PB[kx],     ww);
                        fma2(acc[1][o][1], PB[kx + 2], ww);
                    }
                }
            }
        }

        // store: broadcast to 3 channels, streaming hint
        int b   = t >> 6;
        int rem = t & 63;
        int by  = (rem >> 3) * TILE_H;
        int bx  = (rem & 7) * TILE_W;
        int ox  = bx + tx * 4;
        size_t obase = (size_t)b * 3 * 1024 * 1024;
        #pragma unroll
        for (int g = 0; g < 2; g++) {
            #pragma unroll
            for (int o = 0; o < 4; o++) {
                float4 r4;
                unpk2(acc[g][o][0], r4.x, r4.y);
                unpk2(acc[g][o][1], r4.z, r4.w);
                int oy = by + row0 + g * 64 + o;
                size_t off = obase + (size_t)oy * 1024 + ox;
                #pragma unroll
                for (int c = 0; c < 3; c++)
                    __stcs((float4*)(out + off + (size_t)c * 1024 * 1024), r4);
            }
        }

        __syncthreads();   // buffer reuse protection
        cur ^= 1;
        t = nxt;
    }
}

extern "C" void kernel_launch(void* const* d_in, const int* in_sizes, int n_in,
                              void* d_out, int out_size) {
    const float* img = (const float*)d_in[0];
    const float* ker = (const float*)d_in[1];
    float* out = (float*)d_out;

    cudaFuncSetAttribute(Conv_8443905704574_kernel,
                         cudaFuncAttributeMaxDynamicSharedMemorySize, SMEM_BYTES);
    Conv_8443905704574_kernel<<<GRID_CTAS, 512, SMEM_BYTES>>>(img, ker, out);
}

// round 8
// speedup vs baseline: 1.2805x; 1.0455x over previous
#include <cuda_runtime.h>

#define KS 7
#define PAD 3
#define TILE_W 128
#define TILE_H 64
#define SW 136                     // staged row: gx in [bx-4, bx+132)
#define SH 70
#define ROW_CHUNKS 34              // 34 x 16B per row
#define TCHUNKS (SH * ROW_CHUNKS)  // 2380
#define NTILES 2048                // 8x * 16y * 16b
#define GRID_CTAS 304              // 2 per SM
#define BUF_FLOATS (SH * SW)       // 9520
#define SMEM_BYTES (2 * BUF_FLOATS * 4 + 7 * 8 * 8)

typedef unsigned long long u64;

__device__ __forceinline__ u64 pk2(float lo, float hi) {
    u64 r; asm("mov.b64 %0, {%1,%2};" : "=l"(r) : "f"(lo), "f"(hi)); return r;
}
__device__ __forceinline__ void fma2(u64& d, u64 a, u64 b) {
    asm("fma.rn.f32x2 %0, %1, %2, %0;" : "+l"(d) : "l"(a), "l"(b));
}
__device__ __forceinline__ void unpk2(u64 v, float& lo, float& hi) {
    asm("mov.b64 {%0,%1}, %2;" : "=f"(lo), "=f"(hi) : "l"(v));
}
__device__ __forceinline__ void cpa16(unsigned dst, const float* src, unsigned nbytes) {
    asm volatile("cp.async.ca.shared.global [%0], [%1], 16, %2;"
                 :: "r"(dst), "l"(src), "r"(nbytes) : "memory");
}

extern __shared__ float smem[];

__device__ __forceinline__ void stage_tile(const float* __restrict__ img, int t,
                                           unsigned sbuf, int tid) {
    int b   = t >> 7;
    int rem = t & 127;
    int by  = (rem >> 3) * TILE_H;
    int bx  = (rem & 7) * TILE_W;
    const float* src = img + ((size_t)b * 3 + 2) * (size_t)(1024 * 1024); // last channel

    #pragma unroll
    for (int k = 0; k < 5; k++) {
        int i = tid + k * 512;
        if (i < TCHUNKS) {
            int r  = i / ROW_CHUNKS;
            int c  = i - r * ROW_CHUNKS;
            int gy = by + r - PAD;
            int gx = bx - 4 + c * 4;
            unsigned ok = ((unsigned)gy < 1024u && (unsigned)gx < 1024u) ? 16u : 0u;
            const float* p = src + (size_t)(gy & 1023) * 1024 + (gx & 1023);
            cpa16(sbuf + (unsigned)(r * SW + c * 4) * 4u, p, ok);
        }
    }
    asm volatile("cp.async.commit_group;" ::: "memory");
}

__global__ __launch_bounds__(512, 2)
void Conv_8443905704574_kernel(const float* __restrict__ img,
                               const float* __restrict__ ker,
                               float* __restrict__ out) {
    const int tid = threadIdx.x;
    float* buf0 = smem;
    float* buf1 = smem + BUF_FLOATS;
    u64 (*kw2)[8] = (u64(*)[8])(smem + 2 * BUF_FLOATS);  // [7][8], 64B rows

    if (tid < 56) {
        int ky = tid >> 3, kx = tid & 7;
        float w = (kx < 7) ? ker[ky * 7 + kx] : 0.0f;
        kw2[ky][kx] = pk2(w, w);
    }

    unsigned sbase;
    asm("{ .reg .u64 t; cvta.to.shared.u64 t, %1; cvt.u32.u64 %0, t; }"
        : "=r"(sbase) : "l"(smem));
    const unsigned sb0 = sbase;
    const unsigned sb1 = sbase + BUF_FLOATS * 4;

    const int tx   = tid & 31;   // 4 contiguous x px, 16B/lane (conflict-free)
    const int ty   = tid >> 5;   // 0..15
    const int row0 = ty * 4;     // 4 output rows per thread

    int t = blockIdx.x;
    if (t < NTILES) stage_tile(img, t, sb0, tid);
    int cur = 0;

    while (t < NTILES) {
        int nxt = t + GRID_CTAS;
        if (nxt < NTILES) {
            stage_tile(img, nxt, cur ? sb0 : sb1, tid);
            asm volatile("cp.async.wait_group 1;" ::: "memory");
        } else {
            asm volatile("cp.async.wait_group 0;" ::: "memory");
        }
        __syncthreads();

        const float* B = cur ? buf1 : buf0;

        u64 acc01[4], acc23[4];
        #pragma unroll
        for (int o = 0; o < 4; o++) { acc01[o] = 0ull; acc23[o] = 0ull; }

        // sliding 10-row window; each input row loaded once, feeds up to 4 output rows
        #pragma unroll
        for (int r = 0; r < 10; r++) {
            const float* row = B + (row0 + r) * SW + tx * 4;
            float4 A0 = *(const float4*)(row);
            float4 A1 = *(const float4*)(row + 4);
            float4 A2 = *(const float4*)(row + 8);      // v[8..11]; v[11] unused
            float v[12] = {A0.x, A0.y, A0.z, A0.w, A1.x, A1.y, A1.z, A1.w,
                           A2.x, A2.y, A2.z, A2.w};
            u64 P[9];
            #pragma unroll
            for (int i = 0; i < 9; i++) P[i] = pk2(v[i + 1], v[i + 2]);

            #pragma unroll
            for (int o = 0; o < 4; o++) {
                const int ky = r - o;
                if (ky >= 0 && ky < KS) {
                    // batched weight row: 3x LDS.128 + 1x LDS.64 (broadcast)
                    const u64* wr = &kw2[ky][0];
                    ulonglong2 q0 = *(const ulonglong2*)(wr);
                    ulonglong2 q1 = *(const ulonglong2*)(wr + 2);
                    ulonglong2 q2 = *(const ulonglong2*)(wr + 4);
                    u64 w6 = wr[6];
                    fma2(acc01[o], P[0], q0.x);  fma2(acc23[o], P[2], q0.x);
                    fma2(acc01[o], P[1], q0.y);  fma2(acc23[o], P[3], q0.y);
                    fma2(acc01[o], P[2], q1.x);  fma2(acc23[o], P[4], q1.x);
                    fma2(acc01[o], P[3], q1.y);  fma2(acc23[o], P[5], q1.y);
                    fma2(acc01[o], P[4], q2.x);  fma2(acc23[o], P[6], q2.x);
                    fma2(acc01[o], P[5], q2.y);  fma2(acc23[o], P[7], q2.y);
                    fma2(acc01[o], P[6], w6);    fma2(acc23[o], P[8], w6);
                }
            }
        }

        // Barrier BEFORE stores: smem reads are done; next-tile staging can
        // overlap with the store drain.
        __syncthreads();

        int b   = t >> 7;
        int rem = t & 127;
        int by  = (rem >> 3) * TILE_H;
        int bx  = (rem & 7) * TILE_W;
        int ox  = bx + tx * 4;
        size_t obase = (size_t)b * 3 * 1024 * 1024;
        #pragma unroll
        for (int o = 0; o < 4; o++) {
            float4 r4;
            unpk2(acc01[o], r4.x, r4.y);
            unpk2(acc23[o], r4.z, r4.w);
            size_t off = obase + (size_t)(by + row0 + o) * 1024 + ox;
            #pragma unroll
            for (int c = 0; c < 3; c++)
                __stcs((float4*)(out + off + (size_t)c * 1024 * 1024), r4);
        }

        cur ^= 1;
        t = nxt;
    }
}

extern "C" void kernel_launch(void* const* d_in, const int* in_sizes, int n_in,
                              void* d_out, int out_size) {
    const float* img = (const float*)d_in[0];
    const float* ker = (const float*)d_in[1];
    float* out = (float*)d_out;

    cudaFuncSetAttribute(Conv_8443905704574_kernel,
                         cudaFuncAttributeMaxDynamicSharedMemorySize, SMEM_BYTES);
    Conv_8443905704574_kernel<<<GRID_CTAS, 512, SMEM_BYTES>>>(img, ker, out);
}